// round 11
// baseline (speedup 1.0000x reference)
#include <cuda_runtime.h>
#include <cuda_fp16.h>
#include <cstdint>
#include <cstring>

#define D_DIM   11008
#define K_DIM   172
#define NKB     11           // k16 blocks for GEMM-1 (j = 0..175)
#define BP      72           // smem row pitch in uint32 (288B) — bank-verified
#define THREADS 128
#define SZ      (88 * BP)    // one Bs buffer: 88 pair-rows
#define SMEM_BYTES (2 * SZ * 4)   // 50688: double-buffered Xr

static __device__ __forceinline__ uint32_t h2_bits(__half2 h) {
    uint32_t u;
    memcpy(&u, &h, 4);
    return u;
}

// had_K * (1/sqrt(D)) pre-packed into fp16 m16n8k16 A-fragment order (R9 layout):
//   block (mw, t, kb) -> 32 lanes -> uint4 {a0, a1, a2, a3}, one LDG.128 per (t,kb).
__device__ uint4 g_hKh[4 * 3 * NKB * 32];

__global__ void prep_hk(const float* __restrict__ hK) {
    int idx = blockIdx.x * blockDim.x + threadIdx.x;
    if (idx >= 4 * 3 * NKB * 32) return;
    int lane = idx & 31;
    int kb   = (idx >> 5) % NKB;
    int t    = (idx >> 5) / NKB % 3;
    int mw   = (idx >> 5) / (NKB * 3);
    int q = lane >> 2, p = lane & 3;
    int i  = mw * 48 + t * 16 + q;
    int k0 = 16 * kb + 2 * p;
    const float scale = rsqrtf((float)D_DIM);   // fold 1/sqrt(D) into hK
    float f[8];
    #pragma unroll
    for (int e = 0; e < 8; ++e) {
        int ii = i + ((e >> 1) & 1) * 8;
        int kk = k0 + (e >> 2) * 8 + (e & 1);
        f[e] = (ii < K_DIM && kk < K_DIM) ? hK[ii * K_DIM + kk] * scale : 0.f;
    }
    uint4 r;
    r.x = h2_bits(__floats2half2_rn(f[0], f[1]));
    r.y = h2_bits(__floats2half2_rn(f[2], f[3]));
    r.z = h2_bits(__floats2half2_rn(f[4], f[5]));
    r.w = h2_bits(__floats2half2_rn(f[6], f[7]));
    g_hKh[idx] = r;
}

__global__ __launch_bounds__(THREADS, 3)
void had_mma_kernel(const float* __restrict__ x,
                    float* __restrict__ out,
                    int nrows)
{
    extern __shared__ uint32_t Bs[];   // 2 x [88][BP] half2-pair-packed Xr
    const int tid  = threadIdx.x;
    const int w    = tid >> 5;               // 0..3 (= mw, M-tile)
    const int lane = tid & 31;
    const int q    = lane >> 2;              // 0..7
    const int p    = lane & 3;               // 0..3
    const int G    = gridDim.x;

    // H_64 fragment constants (Sylvester): every fragment is hA or hA^sign-flip.
    const uint32_t pq = (uint32_t)(__popc(p & (q >> 1)) & 1);
    const uint32_t t0 = (uint32_t)(q & 1);
    const uint32_t hA  = 0x3C003C00u | (pq << 15) | ((pq ^ t0) << 31);
    const uint32_t hAf = hA ^ 0x80008000u;

    const uint4* Aw = g_hKh + (size_t)(w * 3) * NKB * 32 + lane;

    // ---------- prologue: load first row into buffer 0 ----------
    int r = blockIdx.x;
    if (r < nrows) {
        const float* xr = x + (size_t)r * D_DIM;
        #pragma unroll
        for (int k2 = 0; k2 < 22; ++k2) {
            const int c2 = w + 4 * k2;
            float c0 = 0.f, c1 = 0.f, d0 = 0.f, d1 = 0.f;
            if (c2 < 86) {
                const float* b0 = xr + (size_t)c2 * 128 + lane;
                c0 = b0[0]; c1 = b0[32]; d0 = b0[64]; d1 = b0[96];
            }
            Bs[c2 * BP + lane]      = h2_bits(__floats2half2_rn(c0, d0));
            Bs[c2 * BP + lane + 32] = h2_bits(__floats2half2_rn(c1, d1));
        }
    }
    __syncthreads();

    int buf = 0;
    for (; r < nrows; r += G, buf ^= 1) {
        const bool pf = (r + G < nrows);
        const float* xn = x + (size_t)(r + G) * D_DIM;
        uint32_t* Bn = Bs + (buf ^ 1) * SZ;
        const uint32_t* Bc = Bs + buf * SZ;

        // ---------- GEMM-1: T = (hK/sqrtD) @ Xr, with interleaved next-row prefetch ----------
        float acc[3][8][4];
        #pragma unroll
        for (int t = 0; t < 3; ++t)
            #pragma unroll
            for (int u = 0; u < 8; ++u)
                #pragma unroll
                for (int e = 0; e < 4; ++e) acc[t][u][e] = 0.f;

        #pragma unroll
        for (int kb = 0; kb < NKB; ++kb) {
            // prefetch 2 of 22 pack-steps for row r+G into the other buffer
            if (pf) {
                #pragma unroll
                for (int s = 0; s < 2; ++s) {
                    const int c2 = w + 4 * (2 * kb + s);
                    float c0 = 0.f, c1 = 0.f, d0 = 0.f, d1 = 0.f;
                    if (c2 < 86) {
                        const float* bsrc = xn + (size_t)c2 * 128 + lane;
                        c0 = bsrc[0]; c1 = bsrc[32]; d0 = bsrc[64]; d1 = bsrc[96];
                    }
                    Bn[c2 * BP + lane]      = h2_bits(__floats2half2_rn(c0, d0));
                    Bn[c2 * BP + lane + 32] = h2_bits(__floats2half2_rn(c1, d1));
                }
            }
            uint32_t b0[8], b1[8];
            const uint32_t* br = Bc + (8 * kb + p) * BP + q;
            #pragma unroll
            for (int u = 0; u < 8; ++u) {
                b0[u] = br[8 * u];                // k = 16kb+2p, +1
                b1[u] = br[8 * u + 4 * BP];       // k = 16kb+2p+8, +9
            }
            #pragma unroll
            for (int t = 0; t < 3; ++t) {
                uint4 a = Aw[(size_t)(t * NKB + kb) * 32];   // one coalesced LDG.128
                #pragma unroll
                for (int u = 0; u < 8; ++u) {
                    asm volatile(
                        "mma.sync.aligned.m16n8k16.row.col.f32.f16.f16.f32 "
                        "{%0,%1,%2,%3}, {%4,%5,%6,%7}, {%8,%9}, {%0,%1,%2,%3};"
                        : "+f"(acc[t][u][0]), "+f"(acc[t][u][1]),
                          "+f"(acc[t][u][2]), "+f"(acc[t][u][3])
                        : "r"(a.x), "r"(a.y), "r"(a.z), "r"(a.w),
                          "r"(b0[u]), "r"(b1[u]));
                }
            }
        }

        // ---------- GEMM-2: out = T @ H_64 (A register-direct, H from 2 registers) ----------
        {
            float* orow = out + (size_t)r * D_DIM;
            const int i0 = w * 48;
            #pragma unroll
            for (int t = 0; t < 3; ++t) {
                float a2c[8][4];
                #pragma unroll
                for (int u = 0; u < 8; ++u)
                    #pragma unroll
                    for (int e = 0; e < 4; ++e) a2c[u][e] = 0.f;

                #pragma unroll
                for (int v = 0; v < 4; ++v) {
                    const uint32_t a0 = h2_bits(__floats2half2_rn(acc[t][2*v  ][0], acc[t][2*v  ][1]));
                    const uint32_t a1 = h2_bits(__floats2half2_rn(acc[t][2*v  ][2], acc[t][2*v  ][3]));
                    const uint32_t a2 = h2_bits(__floats2half2_rn(acc[t][2*v+1][0], acc[t][2*v+1][1]));
                    const uint32_t a3 = h2_bits(__floats2half2_rn(acc[t][2*v+1][2], acc[t][2*v+1][3]));
                    #pragma unroll
                    for (int u = 0; u < 8; ++u) {
                        // s0 = pq ^ c0, c0 = (v&1)&(u>>1) ^ (v>>1)&(u>>2); s1 = s0 ^ (u&1)
                        const int c0s = (((v & 1) & ((u >> 1) & 1)) ^ (((v >> 1) & 1) & ((u >> 2) & 1)));
                        const int c1s = c0s ^ (u & 1);
                        const uint32_t hb0 = c0s ? hAf : hA;
                        const uint32_t hb1 = c1s ? hAf : hA;
                        asm volatile(
                            "mma.sync.aligned.m16n8k16.row.col.f32.f16.f16.f32 "
                            "{%0,%1,%2,%3}, {%4,%5,%6,%7}, {%8,%9}, {%0,%1,%2,%3};"
                            : "+f"(a2c[u][0]), "+f"(a2c[u][1]),
                              "+f"(a2c[u][2]), "+f"(a2c[u][3])
                            : "r"(a0), "r"(a1), "r"(a2), "r"(a3),
                              "r"(hb0), "r"(hb1));
                    }
                }
                // direct store (8-row x 32B runs)
                const int ib = i0 + t * 16 + q;
                #pragma unroll
                for (int u = 0; u < 8; ++u) {
                    const int m = u * 8 + 2 * p;
                    if (ib < K_DIM)
                        *(float2*)(orow + ib * 64 + m) = make_float2(a2c[u][0], a2c[u][1]);
                    if (ib + 8 < K_DIM)
                        *(float2*)(orow + (ib + 8) * 64 + m) = make_float2(a2c[u][2], a2c[u][3]);
                }
            }
        }
        __syncthreads();   // all warps done with Bc; Bn fully written -> swap
    }
}

extern "C" void kernel_launch(void* const* d_in, const int* in_sizes, int n_in,
                              void* d_out, int out_size)
{
    const float* x  = (const float*)d_in[0];
    const float* hK = (const float*)d_in[1];
    int nx = in_sizes[0];
    if (n_in > 1 && in_sizes[0] == K_DIM * K_DIM) {   // defensive input-order check
        x  = (const float*)d_in[1];
        hK = (const float*)d_in[0];
        nx = in_sizes[1];
    }
    float* out = (float*)d_out;
    const int nrows = nx / D_DIM;

    int sms = 148;
    cudaDeviceGetAttribute(&sms, cudaDevAttrMultiProcessorCount, 0);
    int grid = 3 * sms;
    if (grid > nrows) grid = nrows;

    cudaFuncSetAttribute(had_mma_kernel,
                         cudaFuncAttributeMaxDynamicSharedMemorySize, SMEM_BYTES);

    prep_hk<<<(4 * 3 * NKB * 32 + 255) / 256, 256>>>(hK);
    had_mma_kernel<<<grid, THREADS, SMEM_BYTES>>>(x, out, nrows);
}

// round 12
// speedup vs baseline: 1.4809x; 1.4809x over previous
#include <cuda_runtime.h>
#include <cuda_fp16.h>
#include <cstdint>
#include <cstring>

#define D_DIM   11008
#define K_DIM   172
#define NKB     11           // k16 blocks for GEMM-1 (j = 0..175)
#define BP      72           // Bs row pitch in uint32 (288B) — bank-verified
#define THREADS 256
#define PEX     (256 * 17)   // one P-exchange buffer (floats), pitch 17 conflict-free
#define SMEM_BYTES (88 * BP * 4 + 2 * PEX * 4)   // 25344 + 34816 = 60160

static __device__ __forceinline__ uint32_t h2_bits(__half2 h) {
    uint32_t u;
    memcpy(&u, &h, 4);
    return u;
}

// had_K * (1/sqrt(D)) pre-packed into fp16 m16n8k16 A-fragment order (R9 layout):
//   block (mw, t, kb) -> 32 lanes -> uint4 {a0, a1, a2, a3}, one LDG.128 per (t,kb).
__device__ uint4 g_hKh[4 * 3 * NKB * 32];

__global__ void prep_hk(const float* __restrict__ hK) {
    int idx = blockIdx.x * blockDim.x + threadIdx.x;
    if (idx >= 4 * 3 * NKB * 32) return;
    int lane = idx & 31;
    int kb   = (idx >> 5) % NKB;
    int t    = (idx >> 5) / NKB % 3;
    int mw   = (idx >> 5) / (NKB * 3);
    int q = lane >> 2, p = lane & 3;
    int i  = mw * 48 + t * 16 + q;
    int k0 = 16 * kb + 2 * p;
    const float scale = rsqrtf((float)D_DIM);   // fold 1/sqrt(D) into hK
    float f[8];
    #pragma unroll
    for (int e = 0; e < 8; ++e) {
        int ii = i + ((e >> 1) & 1) * 8;
        int kk = k0 + (e >> 2) * 8 + (e & 1);
        f[e] = (ii < K_DIM && kk < K_DIM) ? hK[ii * K_DIM + kk] * scale : 0.f;
    }
    uint4 r;
    r.x = h2_bits(__floats2half2_rn(f[0], f[1]));
    r.y = h2_bits(__floats2half2_rn(f[2], f[3]));
    r.z = h2_bits(__floats2half2_rn(f[4], f[5]));
    r.w = h2_bits(__floats2half2_rn(f[6], f[7]));
    g_hKh[idx] = r;
}

__global__ __launch_bounds__(THREADS, 2)
void had_mma_kernel(const float* __restrict__ x,
                    float* __restrict__ out)
{
    extern __shared__ uint32_t Smem[];
    uint32_t* Bs = Smem;                       // [88][BP] half2 pair-packed Xr
    float* Pex = (float*)(Smem + 88 * BP);     // 2 x [256][17] P-exchange
    const int tid  = threadIdx.x;
    const int w    = tid >> 5;                 // 0..7
    const int lane = tid & 31;
    const int q    = lane >> 2;                // 0..7
    const int p    = lane & 3;                 // 0..3
    const int mw   = w & 3;                    // M-tile: i0 = mw*48
    const int nw   = w >> 2;                   // N-half: cols 32nw..32nw+31
    const int row  = blockIdx.x;

    // H32 fragment constants (Sylvester): every fragment is hA or hA^signflip.
    const uint32_t pq = (uint32_t)(__popc(p & (q >> 1)) & 1);
    const uint32_t t0 = (uint32_t)(q & 1);
    const uint32_t hA  = 0x3C003C00u | (pq << 15) | ((pq ^ t0) << 31);
    const uint32_t hAf = hA ^ 0x80008000u;

    // ---------- Phase 1: load raw Xr -> half2 pair-packed Bs (batch, high MLP) ----------
    // pair c2 = w + 8*k2 (8 warps, k2 = 0..10); c2 >= 86 -> zero pad rows.
    {
        const float* xr = x + (size_t)row * D_DIM;
        #pragma unroll
        for (int k2 = 0; k2 < 11; ++k2) {
            const int c2 = w + 8 * k2;
            float c0 = 0.f, c1 = 0.f, d0 = 0.f, d1 = 0.f;
            if (c2 < 86) {
                const float* b0 = xr + (size_t)c2 * 128 + lane;
                c0 = b0[0]; c1 = b0[32]; d0 = b0[64]; d1 = b0[96];
            }
            Bs[c2 * BP + lane]      = h2_bits(__floats2half2_rn(c0, d0));  // m = lane
            Bs[c2 * BP + lane + 32] = h2_bits(__floats2half2_rn(c1, d1));  // m = lane+32
        }
    }
    __syncthreads();

    // ---------- Phase 2: T = (hK/sqrtD) @ Xr — warp covers rows [mw*48,+48), cols [32nw,+32) ----------
    float acc[3][4][4];
    #pragma unroll
    for (int t = 0; t < 3; ++t)
        #pragma unroll
        for (int u = 0; u < 4; ++u)
            #pragma unroll
            for (int e = 0; e < 4; ++e) acc[t][u][e] = 0.f;

    const uint4* Aw = g_hKh + (size_t)(mw * 3) * NKB * 32 + lane;

    #pragma unroll 2
    for (int kb = 0; kb < NKB; ++kb) {
        uint32_t b0[4], b1[4];
        const uint32_t* br = Bs + (8 * kb + p) * BP + 32 * nw + q;
        #pragma unroll
        for (int u = 0; u < 4; ++u) {
            b0[u] = br[8 * u];                // k = 16kb+2p, +1
            b1[u] = br[8 * u + 4 * BP];       // k = 16kb+2p+8, +9
        }
        #pragma unroll
        for (int t = 0; t < 3; ++t) {
            uint4 a = Aw[(size_t)(t * NKB + kb) * 32];   // one coalesced LDG.128 (L1/L2 broadcast)
            #pragma unroll
            for (int u = 0; u < 4; ++u) {
                asm volatile(
                    "mma.sync.aligned.m16n8k16.row.col.f32.f16.f16.f32 "
                    "{%0,%1,%2,%3}, {%4,%5,%6,%7}, {%8,%9}, {%0,%1,%2,%3};"
                    : "+f"(acc[t][u][0]), "+f"(acc[t][u][1]),
                      "+f"(acc[t][u][2]), "+f"(acc[t][u][3])
                    : "r"(a.x), "r"(a.y), "r"(a.z), "r"(a.w),
                      "r"(b0[u]), "r"(b1[u]));
            }
        }
    }

    // ---------- Phase 3: out = T @ H64 via H64 = H32 (x) H2 ----------
    // P_nw = T[:, 32nw:32nw+32] @ H32 (register A from acc, register H, 2 k-steps).
    // Exchange P with partner warp (w^4, same fragment coords), combine P0 +- P1, store.
    {
        float* orow = out + (size_t)row * D_DIM;
        const int i0 = mw * 48;
        float* myP = Pex + (w * 32 + lane) * 17;
        const float* thP = Pex + (((w ^ 4) * 32) + lane) * 17;

        #pragma unroll
        for (int t = 0; t < 3; ++t) {
            const int pb = (t & 1) * PEX;    // double-buffered exchange
            float a2c[4][4];
            #pragma unroll
            for (int u = 0; u < 4; ++u)
                #pragma unroll
                for (int e = 0; e < 4; ++e) a2c[u][e] = 0.f;

            #pragma unroll
            for (int v = 0; v < 2; ++v) {    // K = 32 -> 2 k16 steps
                const uint32_t a0 = h2_bits(__floats2half2_rn(acc[t][2*v  ][0], acc[t][2*v  ][1]));
                const uint32_t a1 = h2_bits(__floats2half2_rn(acc[t][2*v  ][2], acc[t][2*v  ][3]));
                const uint32_t a2 = h2_bits(__floats2half2_rn(acc[t][2*v+1][0], acc[t][2*v+1][1]));
                const uint32_t a3 = h2_bits(__floats2half2_rn(acc[t][2*v+1][2], acc[t][2*v+1][3]));
                #pragma unroll
                for (int u = 0; u < 4; ++u) {
                    const int flip = v & (u >> 1);            // H32 sign: v&(u'>>1)
                    const uint32_t hb0 = flip ? hAf : hA;
                    const uint32_t hb1 = (flip ^ (u & 1)) ? hAf : hA;
                    asm volatile(
                        "mma.sync.aligned.m16n8k16.row.col.f32.f16.f16.f32 "
                        "{%0,%1,%2,%3}, {%4,%5,%6,%7}, {%8,%9}, {%0,%1,%2,%3};"
                        : "+f"(a2c[u][0]), "+f"(a2c[u][1]),
                          "+f"(a2c[u][2]), "+f"(a2c[u][3])
                        : "r"(a0), "r"(a1), "r"(a2), "r"(a3),
                          "r"(hb0), "r"(hb1));
                }
            }
            // exchange P with partner warp
            #pragma unroll
            for (int u = 0; u < 4; ++u)
                #pragma unroll
                for (int e = 0; e < 4; ++e)
                    myP[pb + u * 4 + e] = a2c[u][e];
            __syncthreads();
            // combine: out[:,0:32] = P0+P1 (nw=0), out[:,32:64] = P0-P1 (nw=1)
            const int ib = i0 + t * 16 + q;
            #pragma unroll
            for (int u = 0; u < 4; ++u) {
                float c[4];
                #pragma unroll
                for (int e = 0; e < 4; ++e) {
                    float th = thP[pb + u * 4 + e];
                    c[e] = nw ? (th - a2c[u][e]) : (a2c[u][e] + th);
                }
                const int m = 32 * nw + 8 * u + 2 * p;
                if (ib < K_DIM)
                    *(float2*)(orow + ib * 64 + m) = make_float2(c[0], c[1]);
                if (ib + 8 < K_DIM)
                    *(float2*)(orow + (ib + 8) * 64 + m) = make_float2(c[2], c[3]);
            }
        }
    }
}

extern "C" void kernel_launch(void* const* d_in, const int* in_sizes, int n_in,
                              void* d_out, int out_size)
{
    const float* x  = (const float*)d_in[0];
    const float* hK = (const float*)d_in[1];
    int nx = in_sizes[0];
    if (n_in > 1 && in_sizes[0] == K_DIM * K_DIM) {   // defensive input-order check
        x  = (const float*)d_in[1];
        hK = (const float*)d_in[0];
        nx = in_sizes[1];
    }
    float* out = (float*)d_out;
    const int nrows = nx / D_DIM;

    cudaFuncSetAttribute(had_mma_kernel,
                         cudaFuncAttributeMaxDynamicSharedMemorySize, SMEM_BYTES);

    prep_hk<<<(4 * 3 * NKB * 32 + 255) / 256, 256>>>(hK);
    had_mma_kernel<<<nrows, THREADS, SMEM_BYTES>>>(x, out);
}

// round 13
// speedup vs baseline: 1.9885x; 1.3427x over previous
#include <cuda_runtime.h>
#include <cuda_fp16.h>
#include <cstdint>
#include <cstring>

#define D_DIM   11008
#define K_DIM   172
#define NKB     11           // k16 blocks for GEMM-1 (j = 0..175)
#define BP      72           // Bs row pitch in uint32 (288B) — bank-verified
#define THREADS 128
#define SMEM_BYTES (88 * BP * 4)   // 25344

static __device__ __forceinline__ uint32_t h2_bits(__half2 h) {
    uint32_t u;
    memcpy(&u, &h, 4);
    return u;
}

// had_K * (1/sqrt(D)) pre-packed into fp16 m16n8k16 A-fragment order (R9 layout):
//   block (mw, t, kb) -> 32 lanes -> uint4 {a0, a1, a2, a3}, one LDG.128 per (t,kb).
__device__ uint4 g_hKh[4 * 3 * NKB * 32];

__global__ void prep_hk(const float* __restrict__ hK) {
    int idx = blockIdx.x * blockDim.x + threadIdx.x;
    if (idx >= 4 * 3 * NKB * 32) return;
    int lane = idx & 31;
    int kb   = (idx >> 5) % NKB;
    int t    = (idx >> 5) / NKB % 3;
    int mw   = (idx >> 5) / (NKB * 3);
    int q = lane >> 2, p = lane & 3;
    int i  = mw * 48 + t * 16 + q;
    int k0 = 16 * kb + 2 * p;
    const float scale = rsqrtf((float)D_DIM);   // fold 1/sqrt(D) into hK
    float f[8];
    #pragma unroll
    for (int e = 0; e < 8; ++e) {
        int ii = i + ((e >> 1) & 1) * 8;
        int kk = k0 + (e >> 2) * 8 + (e & 1);
        f[e] = (ii < K_DIM && kk < K_DIM) ? hK[ii * K_DIM + kk] * scale : 0.f;
    }
    uint4 r;
    r.x = h2_bits(__floats2half2_rn(f[0], f[1]));
    r.y = h2_bits(__floats2half2_rn(f[2], f[3]));
    r.z = h2_bits(__floats2half2_rn(f[4], f[5]));
    r.w = h2_bits(__floats2half2_rn(f[6], f[7]));
    g_hKh[idx] = r;
}

__global__ __launch_bounds__(THREADS, 3)
void had_mma_kernel(const float* __restrict__ x,
                    float* __restrict__ out)
{
    extern __shared__ uint32_t Bs[];   // [88][BP] half2 pair-packed Xr
    const int tid  = threadIdx.x;
    const int w    = tid >> 5;               // 0..3 (= mw, M-tile)
    const int lane = tid & 31;
    const int q    = lane >> 2;              // 0..7
    const int p    = lane & 3;               // 0..3
    const int row  = blockIdx.x;

    // H_64 fragment constants (Sylvester, R11-validated): hA or hA^signflip.
    const uint32_t pq = (uint32_t)(__popc(p & (q >> 1)) & 1);
    const uint32_t t0 = (uint32_t)(q & 1);
    const uint32_t hA  = 0x3C003C00u | (pq << 15) | ((pq ^ t0) << 31);
    const uint32_t hAf = hA ^ 0x80008000u;

    // ---------- Phase 1: float4 bulk load -> half2 pair-packed Bs ----------
    // pair-row c2 = 2w + s + 8k2 (s = lane>>4, k2 = 0..10); c2 >= 86 -> zero pad.
    // Bs[c2][m] = {xr[c2*128 + m], xr[c2*128 + 64 + m]}   (m = 4*mg .. 4*mg+3)
    {
        const float* xr = x + (size_t)row * D_DIM;
        const int s  = lane >> 4;            // 0..1
        const int mg = lane & 15;            // m/4 group
        #pragma unroll
        for (int k2 = 0; k2 < 11; ++k2) {
            const int c2 = 2 * w + s + 8 * k2;
            float4 lo = make_float4(0.f, 0.f, 0.f, 0.f);
            float4 hi = lo;
            if (c2 < 86) {
                const float* bp = xr + (size_t)c2 * 128 + 4 * mg;
                lo = *(const float4*)(bp);
                hi = *(const float4*)(bp + 64);
            }
            uint4 pk;
            pk.x = h2_bits(__floats2half2_rn(lo.x, hi.x));
            pk.y = h2_bits(__floats2half2_rn(lo.y, hi.y));
            pk.z = h2_bits(__floats2half2_rn(lo.z, hi.z));
            pk.w = h2_bits(__floats2half2_rn(lo.w, hi.w));
            *(uint4*)(Bs + c2 * BP + 4 * mg) = pk;
        }
    }
    __syncthreads();

    // ---------- Phase 2: T = (hK/sqrtD) @ Xr via m16n8k16 fp16 (4M x 1N warps) ----------
    float acc[3][8][4];
    #pragma unroll
    for (int t = 0; t < 3; ++t)
        #pragma unroll
        for (int u = 0; u < 8; ++u)
            #pragma unroll
            for (int e = 0; e < 4; ++e) acc[t][u][e] = 0.f;

    const uint4* Aw = g_hKh + (size_t)(w * 3) * NKB * 32 + lane;

    #pragma unroll 2
    for (int kb = 0; kb < NKB; ++kb) {
        uint32_t b0[8], b1[8];
        const uint32_t* br = Bs + (8 * kb + p) * BP + q;
        #pragma unroll
        for (int u = 0; u < 8; ++u) {
            b0[u] = br[8 * u];                // k = 16kb+2p, +1
            b1[u] = br[8 * u + 4 * BP];       // k = 16kb+2p+8, +9
        }
        #pragma unroll
        for (int t = 0; t < 3; ++t) {
            uint4 a = Aw[(size_t)(t * NKB + kb) * 32];   // one coalesced LDG.128
            #pragma unroll
            for (int u = 0; u < 8; ++u) {
                asm volatile(
                    "mma.sync.aligned.m16n8k16.row.col.f32.f16.f16.f32 "
                    "{%0,%1,%2,%3}, {%4,%5,%6,%7}, {%8,%9}, {%0,%1,%2,%3};"
                    : "+f"(acc[t][u][0]), "+f"(acc[t][u][1]),
                      "+f"(acc[t][u][2]), "+f"(acc[t][u][3])
                    : "r"(a.x), "r"(a.y), "r"(a.z), "r"(a.w),
                      "r"(b0[u]), "r"(b1[u]));
            }
        }
    }

    // ---------- Phase 3: out = T @ H_64 (A register-direct, H from 2 registers) ----------
    {
        float* orow = out + (size_t)row * D_DIM;
        const int i0 = w * 48;
        #pragma unroll
        for (int t = 0; t < 3; ++t) {
            float a2c[8][4];
            #pragma unroll
            for (int u = 0; u < 8; ++u)
                #pragma unroll
                for (int e = 0; e < 4; ++e) a2c[u][e] = 0.f;

            #pragma unroll
            for (int v = 0; v < 4; ++v) {
                const uint32_t a0 = h2_bits(__floats2half2_rn(acc[t][2*v  ][0], acc[t][2*v  ][1]));
                const uint32_t a1 = h2_bits(__floats2half2_rn(acc[t][2*v  ][2], acc[t][2*v  ][3]));
                const uint32_t a2 = h2_bits(__floats2half2_rn(acc[t][2*v+1][0], acc[t][2*v+1][1]));
                const uint32_t a3 = h2_bits(__floats2half2_rn(acc[t][2*v+1][2], acc[t][2*v+1][3]));
                #pragma unroll
                for (int u = 0; u < 8; ++u) {
                    // sign flips (R11-validated): c0 = (v&1)&(u>>1 & 1) ^ (v>>1 & 1)&(u>>2 & 1)
                    const int c0s = (((v & 1) & ((u >> 1) & 1)) ^ (((v >> 1) & 1) & ((u >> 2) & 1)));
                    const int c1s = c0s ^ (u & 1);
                    const uint32_t hb0 = c0s ? hAf : hA;
                    const uint32_t hb1 = c1s ? hAf : hA;
                    asm volatile(
                        "mma.sync.aligned.m16n8k16.row.col.f32.f16.f16.f32 "
                        "{%0,%1,%2,%3}, {%4,%5,%6,%7}, {%8,%9}, {%0,%1,%2,%3};"
                        : "+f"(a2c[u][0]), "+f"(a2c[u][1]),
                          "+f"(a2c[u][2]), "+f"(a2c[u][3])
                        : "r"(a0), "r"(a1), "r"(a2), "r"(a3),
                          "r"(hb0), "r"(hb1));
                }
            }
            // direct store (8-row x 32B runs)
            const int ib = i0 + t * 16 + q;
            #pragma unroll
            for (int u = 0; u < 8; ++u) {
                const int m = u * 8 + 2 * p;
                if (ib < K_DIM)
                    *(float2*)(orow + ib * 64 + m) = make_float2(a2c[u][0], a2c[u][1]);
                if (ib + 8 < K_DIM)
                    *(float2*)(orow + (ib + 8) * 64 + m) = make_float2(a2c[u][2], a2c[u][3]);
            }
        }
    }
}

extern "C" void kernel_launch(void* const* d_in, const int* in_sizes, int n_in,
                              void* d_out, int out_size)
{
    const float* x  = (const float*)d_in[0];
    const float* hK = (const float*)d_in[1];
    int nx = in_sizes[0];
    if (n_in > 1 && in_sizes[0] == K_DIM * K_DIM) {   // defensive input-order check
        x  = (const float*)d_in[1];
        hK = (const float*)d_in[0];
        nx = in_sizes[1];
    }
    float* out = (float*)d_out;
    const int nrows = nx / D_DIM;

    cudaFuncSetAttribute(had_mma_kernel,
                         cudaFuncAttributeMaxDynamicSharedMemorySize, SMEM_BYTES);

    prep_hk<<<(4 * 3 * NKB * 32 + 255) / 256, 256>>>(hK);
    had_mma_kernel<<<nrows, THREADS, SMEM_BYTES>>>(x, out);
}